// round 9
// baseline (speedup 1.0000x reference)
#include <cuda_runtime.h>
#include <cstdint>
#include <cstring>

#define KK 16
#define FF 32
#define NT 64
#define NTHREADS 256
#define NWARP (NTHREADS/32)

__device__ __forceinline__ float warpsum(float v){
  #pragma unroll
  for (int o = 16; o > 0; o >>= 1) v += __shfl_xor_sync(0xffffffffu, v, o);
  return v;
}

__device__ __forceinline__ float grp8sum(float v){
  v += __shfl_xor_sync(0xffffffffu, v, 1);
  v += __shfl_xor_sync(0xffffffffu, v, 2);
  v += __shfl_xor_sync(0xffffffffu, v, 4);
  return v;
}

// packed f32x2 ops (sm_100+; not reachable from C++)
__device__ __forceinline__ unsigned long long ffma2(unsigned long long a,
                                                    unsigned long long b,
                                                    unsigned long long c){
  unsigned long long d;
  asm("fma.rn.f32x2 %0, %1, %2, %3;" : "=l"(d) : "l"(a), "l"(b), "l"(c));
  return d;
}
__device__ __forceinline__ unsigned long long fmul2(unsigned long long a,
                                                    unsigned long long b){
  unsigned long long d;
  asm("mul.rn.f32x2 %0, %1, %2;" : "=l"(d) : "l"(a), "l"(b));
  return d;
}
__device__ __forceinline__ unsigned long long fadd2(unsigned long long a,
                                                    unsigned long long b){
  unsigned long long d;
  asm("add.rn.f32x2 %0, %1, %2;" : "=l"(d) : "l"(a), "l"(b));
  return d;
}
__device__ __forceinline__ float2 unpack2(unsigned long long a){
  float2 f;
  asm("mov.b64 {%0, %1}, %2;" : "=f"(f.x), "=f"(f.y) : "l"(a));
  return f;
}
__device__ __forceinline__ unsigned long long pack2(float lo, float hi){
  unsigned long long d;
  asm("mov.b64 %0, {%1, %2};" : "=l"(d) : "f"(lo), "f"(hi));
  return d;
}

__device__ __forceinline__ uint32_t smem_u32(const void* p){
  uint32_t a;
  asm("{ .reg .u64 t; cvta.to.shared.u64 t, %1; cvt.u32.u64 %0, t; }"
      : "=r"(a) : "l"(p));
  return a;
}

__device__ __forceinline__ void cp_async16(uint32_t dst, const void* src){
  asm volatile("cp.async.cg.shared.global [%0], [%1], 16;"
               :: "r"(dst), "l"(src));
}

// int64 vs int32 index array detection (node ids < 2^31)
__device__ __forceinline__ int is64_flag(const void* p){
  const unsigned int* u = (const unsigned int*)p;
  return ((u[1] | u[3] | u[5] | u[7]) == 0u) ? 1 : 0;
}
__device__ __forceinline__ int ldidx32(const void* p, int i, int is64){
  return is64 ? ((const int*)p)[2 * i] : ((const int*)p)[i];
}

struct Params {
  const float* x;
  const void* sel[4];
  const void* nei[4];
  const float* Wf[4];
  const float* Wn[4];
  float* out;
  int Nd[4];
  int bound[3];   // exclusive block-prefix: [deg4), [deg4+deg3), [.. +deg2)
};

// Uniform tile config for all degrees: TN=4 nodes x TK=4 kernels, FS=4 feature split.
template<int DEG>
__device__ __forceinline__ void body(const Params& p, int tileIdx)
{
  constexpr int RPG  = 1 + DEG;
  constexpr int L    = RPG * FF;
  constexpr int LP   = L + 4;           // 16B-aligned stride, ==4 (mod 8)
  constexpr int RTOT = NT * RPG;
  constexpr int TN = 4, TK = 4;

  const float* __restrict__ x   = p.x;
  const void*  __restrict__ sel = p.sel[DEG - 1];
  const void*  __restrict__ nei = p.nei[DEG - 1];
  const float* __restrict__ Wf  = p.Wf[DEG - 1];
  const float* __restrict__ Wn  = p.Wn[DEG - 1];
  float* __restrict__ out = p.out;
  const int Nd = p.Nd[DEG - 1];

  extern __shared__ float smem[];
  float* Xs = smem;                               // NT * LP
  float* Ws = smem + NT * LP;                     // KK * LP
  int*   Rs = (int*)(smem + NT * LP + KK * LP);   // RTOT row ids

  const int tid  = threadIdx.x;
  const int w    = tid >> 5;
  const int lane = tid & 31;
  const int tile = tileIdx * NT;
  const int count = min(NT, Nd - tile);
  const int s64 = is64_flag(sel);
  const int n64 = is64_flag(nei);

  // ---- Phase A: stage row ids into SMEM (coalesced).
  #pragma unroll
  for (int r = tid; r < RTOT; r += NTHREADS){
    const int nn = r / RPG, ss = r - nn * RPG;
    int id = 0;
    if (nn < count)
      id = (ss == 0) ? ldidx32(sel, tile + nn, s64)
                     : ldidx32(nei, (tile + nn) * DEG + ss - 1, n64);
    Rs[r] = id;
  }
  __syncthreads();

  // ---- Phase B: whole gather via cp.async (GMEM -> SMEM, no RF).
  {
    const int c  = tid & 7;
    const int rb = tid >> 3;
    constexpr int ITER = RTOT / 32;
    constexpr int DNN = 32 / RPG, DSS = 32 % RPG;
    const uint32_t xs0 = smem_u32(Xs) + (uint32_t)(c * 16);
    int nn = rb / RPG, ss = rb - nn * RPG;
    #pragma unroll
    for (int i = 0; i < ITER; i++){
      if (nn < count){
        const unsigned id = (unsigned)Rs[rb + 32 * i];
        const float* src = x + (size_t)(id * (unsigned)FF) + c * 4;
        const uint32_t dst = xs0 + (uint32_t)((nn * LP + ss * FF) * 4);
        cp_async16(dst, src);
      }
      ss += DSS;
      const int wrap = (ss >= RPG);
      if (wrap) ss -= RPG;
      nn += DNN + wrap;
    }
    asm volatile("cp.async.commit_group;");
  }

  // ---- Phase 0 (overlaps gather): normalize weights into SMEM.
  {
    constexpr int RW = KK * RPG;
    for (int r = w; r < RW; r += NWARP){
      const int k = r / RPG, s = r % RPG;
      float v = (s == 0) ? Wf[k * FF + lane]
                         : Wn[(k * DEG + (s - 1)) * FF + lane];
      const float ss2 = warpsum(v * v);
      float sc = rsqrtf(ss2);
      if (s) sc *= (1.0f / DEG);
      Ws[k * LP + s * FF + lane] = v * sc;
    }
  }

  asm volatile("cp.async.wait_group 0;" ::: "memory");
  __syncthreads();

  // ---- Phase C: L2-normalize rows in place (packed f32x2 math).
  {
    constexpr int G = RTOT / 4;
    const int c  = lane & 7;
    const int rg = lane >> 3;
    #pragma unroll 1
    for (int g0 = w; g0 < G; g0 += NWARP * 4){
      ulonglong2 v[4]; int off[4]; bool val[4];
      #pragma unroll
      for (int u = 0; u < 4; u++){
        const int g = g0 + u * NWARP;
        const int r = g * 4 + rg;
        const int nn = r / RPG, ss = r - nn * RPG;
        val[u] = (g < G) && (nn < count);
        off[u] = nn * LP + ss * FF + c * 4;
        if (val[u]) v[u] = *(const ulonglong2*)&Xs[off[u]];
        else { v[u].x = 0ULL; v[u].y = 0ULL; }
      }
      #pragma unroll
      for (int u = 0; u < 4; u++){
        const unsigned long long sq = ffma2(v[u].y, v[u].y, fmul2(v[u].x, v[u].x));
        const float2 sp = unpack2(sq);
        const float ssq = grp8sum(sp.x + sp.y);
        const float sc = (ssq > 0.0f) ? rsqrtf(ssq) : 0.0f;
        if (val[u]){
          const unsigned long long sc2 = pack2(sc, sc);
          ulonglong2 o;
          o.x = fmul2(v[u].x, sc2);
          o.y = fmul2(v[u].y, sc2);
          *(ulonglong2*)&Xs[off[u]] = o;
        }
      }
    }
  }
  __syncthreads();

  // ---- Phase 2: register-tiled GEMM (f32x2), feature-split 4-ways across lanes;
  // fs==0 lanes write the FULL 256B output row (scores + zeros).
  {
    const int kg  = lane >> 3;           // 4 kernel groups
    const int fs  = (lane >> 1) & 3;     // 4-way feature split
    const int ng  = (w << 1) | (lane & 1);

    unsigned long long acc[TN][TK];
    #pragma unroll
    for (int i = 0; i < TN; i++)
      #pragma unroll
      for (int j = 0; j < TK; j++) acc[i][j] = 0ULL;

    const float* xb = Xs + (ng * TN) * LP + fs * 4;
    const float* wb = Ws + (kg * TK) * LP + fs * 4;
    constexpr int CHUNKS = L / 16;

    #pragma unroll
    for (int cidx = 0; cidx < CHUNKS; cidx++){
      const int off = cidx * 16;
      ulonglong2 xv[TN], wv[TK];
      #pragma unroll
      for (int i = 0; i < TN; i++)
        xv[i] = *(const ulonglong2*)(xb + i * LP + off);
      #pragma unroll
      for (int j = 0; j < TK; j++)
        wv[j] = *(const ulonglong2*)(wb + j * LP + off);
      #pragma unroll
      for (int i = 0; i < TN; i++){
        #pragma unroll
        for (int j = 0; j < TK; j++){
          acc[i][j] = ffma2(xv[i].x, wv[j].x, acc[i][j]);
          acc[i][j] = ffma2(xv[i].y, wv[j].y, acc[i][j]);
        }
      }
    }

    // cross-fs reduction (fs lives in lane bits [2:1])
    #pragma unroll
    for (int mask = 2; mask <= 4; mask <<= 1){
      #pragma unroll
      for (int i = 0; i < TN; i++)
        #pragma unroll
        for (int j = 0; j < TK; j++){
          unsigned long long o = __shfl_xor_sync(0xffffffffu, acc[i][j], mask);
          acc[i][j] = fadd2(acc[i][j], o);
        }
    }

    if (fs == 0){
      #pragma unroll
      for (int i = 0; i < TN; i++){
        const int n = ng * TN + i;
        if (n < count){
          const unsigned node = (unsigned)Rs[n * RPG];
          float4 sv;
          { const float2 a = unpack2(acc[i][0]); sv.x = a.x + a.y; }
          { const float2 a = unpack2(acc[i][1]); sv.y = a.x + a.y; }
          { const float2 a = unpack2(acc[i][2]); sv.z = a.x + a.y; }
          { const float2 a = unpack2(acc[i][3]); sv.w = a.x + a.y; }
          float* row = &out[(size_t)(node * 64u)];
          const float4 z = make_float4(0.f, 0.f, 0.f, 0.f);
          // writer kg covers float4 slots {kg, kg+4, kg+8, kg+12}; the slot with
          // m == DEG-1 is this kg's score block, the rest are zeros.
          #pragma unroll
          for (int m = 0; m < 4; m++)
            *(float4*)&row[(kg + 4 * m) * 4] = (m == DEG - 1) ? sv : z;
        }
      }
    }
  }
}

__global__ void __launch_bounds__(NTHREADS, 3) fused_kernel(Params p)
{
  const int b = blockIdx.x;
  if (b < p.bound[0])            body<4>(p, b);
  else if (b < p.bound[1])       body<3>(p, b - p.bound[0]);
  else if (b < p.bound[2])       body<2>(p, b - p.bound[1]);
  else                           body<1>(p, b - p.bound[2]);
}

static inline int smem_bytes_deg(int deg){
  const int LP = (1 + deg) * FF + 4;
  const int RTOT = NT * (1 + deg);
  return ((NT + KK) * LP) * (int)sizeof(float) + RTOT * (int)sizeof(int);
}

extern "C" void kernel_launch(void* const* d_in, const int* in_sizes, int n_in,
                              void* d_out, int out_size)
{
  Params p;
  p.x = (const float*)d_in[0];

  if (in_sizes[1] == 512){
    // reference-signature order: x, (Wf,Wn)x4, sel1..4, nei1..4
    for (int d = 0; d < 4; d++){
      p.Wf[d]  = (const float*)d_in[1 + 2 * d];
      p.Wn[d]  = (const float*)d_in[2 + 2 * d];
      p.sel[d] = d_in[9 + d];
      p.nei[d] = d_in[13 + d];
      p.Nd[d]  = in_sizes[9 + d];
    }
  } else {
    // setup_inputs dict order: x, then (sel, nei, Wf, Wn) per degree
    int b = 1;
    for (int d = 0; d < 4; d++){
      p.sel[d] = d_in[b + 0];
      p.nei[d] = d_in[b + 1];
      p.Wf[d]  = (const float*)d_in[b + 2];
      p.Wn[d]  = (const float*)d_in[b + 3];
      p.Nd[d]  = in_sizes[b + 0];
      b += 4;
    }
  }
  // int64 storage reports 2x element count in some harnesses; normalize Nd by
  // detecting: Nd counts must sum (with nei) consistently — sel size is element
  // count per metadata; keep as-is.

  p.out = (float*)d_out;

  const int g4 = (p.Nd[3] + NT - 1) / NT;
  const int g3 = (p.Nd[2] + NT - 1) / NT;
  const int g2 = (p.Nd[1] + NT - 1) / NT;
  const int g1 = (p.Nd[0] + NT - 1) / NT;
  p.bound[0] = g4;
  p.bound[1] = g4 + g3;
  p.bound[2] = g4 + g3 + g2;
  const int grid = g4 + g3 + g2 + g1;

  const int smem = smem_bytes_deg(4);   // uniform max (deg4 layout)
  cudaFuncSetAttribute(fused_kernel, cudaFuncAttributeMaxDynamicSharedMemorySize, smem);
  fused_kernel<<<grid, NTHREADS, smem>>>(p);
}

// round 10
// speedup vs baseline: 1.0100x; 1.0100x over previous
#include <cuda_runtime.h>
#include <cstdint>
#include <cstring>

#define KK 16
#define FF 32
#define NT 64
#define NTHREADS 256
#define NWARP (NTHREADS/32)

__device__ __forceinline__ float warpsum(float v){
  #pragma unroll
  for (int o = 16; o > 0; o >>= 1) v += __shfl_xor_sync(0xffffffffu, v, o);
  return v;
}

__device__ __forceinline__ float grp8sum(float v){
  v += __shfl_xor_sync(0xffffffffu, v, 1);
  v += __shfl_xor_sync(0xffffffffu, v, 2);
  v += __shfl_xor_sync(0xffffffffu, v, 4);
  return v;
}

// packed f32x2 ops (sm_100+; not reachable from C++)
__device__ __forceinline__ unsigned long long ffma2(unsigned long long a,
                                                    unsigned long long b,
                                                    unsigned long long c){
  unsigned long long d;
  asm("fma.rn.f32x2 %0, %1, %2, %3;" : "=l"(d) : "l"(a), "l"(b), "l"(c));
  return d;
}
__device__ __forceinline__ unsigned long long fmul2(unsigned long long a,
                                                    unsigned long long b){
  unsigned long long d;
  asm("mul.rn.f32x2 %0, %1, %2;" : "=l"(d) : "l"(a), "l"(b));
  return d;
}
__device__ __forceinline__ unsigned long long fadd2(unsigned long long a,
                                                    unsigned long long b){
  unsigned long long d;
  asm("add.rn.f32x2 %0, %1, %2;" : "=l"(d) : "l"(a), "l"(b));
  return d;
}
__device__ __forceinline__ float2 unpack2(unsigned long long a){
  float2 f;
  asm("mov.b64 {%0, %1}, %2;" : "=f"(f.x), "=f"(f.y) : "l"(a));
  return f;
}
__device__ __forceinline__ unsigned long long pack2(float lo, float hi){
  unsigned long long d;
  asm("mov.b64 %0, {%1, %2};" : "=l"(d) : "f"(lo), "f"(hi));
  return d;
}

__device__ __forceinline__ uint32_t smem_u32(const void* p){
  uint32_t a;
  asm("{ .reg .u64 t; cvta.to.shared.u64 t, %1; cvt.u32.u64 %0, t; }"
      : "=r"(a) : "l"(p));
  return a;
}

__device__ __forceinline__ void cp_async16(uint32_t dst, const void* src){
  asm volatile("cp.async.cg.shared.global [%0], [%1], 16;"
               :: "r"(dst), "l"(src));
}

// int64 vs int32 index array detection (node ids < 2^31)
__device__ __forceinline__ int is64_flag(const void* p){
  const unsigned int* u = (const unsigned int*)p;
  return ((u[1] | u[3] | u[5] | u[7]) == 0u) ? 1 : 0;
}
__device__ __forceinline__ int ldidx32(const void* p, int i, int is64){
  return is64 ? ((const int*)p)[2 * i] : ((const int*)p)[i];
}

// DEG: degree; TN x TK: per-thread node x kernel tile; FS: feature-split ways.
template<int DEG, int TN, int TK, int FS, int MINB>
__global__ void __launch_bounds__(NTHREADS, MINB) score_kernel(
    const float* __restrict__ x,
    const void* __restrict__ sel,
    const void* __restrict__ nei,
    const float* __restrict__ Wf,
    const float* __restrict__ Wn,
    float* __restrict__ out,
    int Nd)
{
  constexpr int RPG  = 1 + DEG;
  constexpr int L    = RPG * FF;
  constexpr int LP   = L + 4;           // 16B-aligned stride, ==4 (mod 8)
  constexpr int RTOT = NT * RPG;

  extern __shared__ float smem[];
  float* Xs = smem;                               // NT * LP
  float* Ws = smem + NT * LP;                     // KK * LP
  int*   Rs = (int*)(smem + NT * LP + KK * LP);   // RTOT row ids

  const int tid  = threadIdx.x;
  const int w    = tid >> 5;
  const int lane = tid & 31;
  const int tile = blockIdx.x * NT;
  const int count = min(NT, Nd - tile);
  const int s64 = is64_flag(sel);
  const int n64 = is64_flag(nei);

  // ---- Phase A: stage row ids into SMEM (coalesced).
  #pragma unroll
  for (int r = tid; r < RTOT; r += NTHREADS){
    const int nn = r / RPG, ss = r - nn * RPG;
    int id = 0;
    if (nn < count)
      id = (ss == 0) ? ldidx32(sel, tile + nn, s64)
                     : ldidx32(nei, (tile + nn) * DEG + ss - 1, n64);
    Rs[r] = id;
  }
  __syncthreads();

  // ---- Phase B: whole gather via cp.async (GMEM -> SMEM, no RF).
  {
    const int c  = tid & 7;
    const int rb = tid >> 3;
    constexpr int ITER = RTOT / 32;
    constexpr int DNN = 32 / RPG, DSS = 32 % RPG;
    const uint32_t xs0 = smem_u32(Xs) + (uint32_t)(c * 16);
    int nn = rb / RPG, ss = rb - nn * RPG;
    #pragma unroll
    for (int i = 0; i < ITER; i++){
      if (nn < count){
        const unsigned id = (unsigned)Rs[rb + 32 * i];
        const float* src = x + (size_t)(id * (unsigned)FF) + c * 4;
        const uint32_t dst = xs0 + (uint32_t)((nn * LP + ss * FF) * 4);
        cp_async16(dst, src);
      }
      ss += DSS;
      const int wrap = (ss >= RPG);
      if (wrap) ss -= RPG;
      nn += DNN + wrap;
    }
    asm volatile("cp.async.commit_group;");
  }

  // ---- Phase 0 (overlaps gather): normalize weights into SMEM.
  {
    constexpr int RW = KK * RPG;
    for (int r = w; r < RW; r += NWARP){
      const int k = r / RPG, s = r % RPG;
      float v = (s == 0) ? Wf[k * FF + lane]
                         : Wn[(k * DEG + (s - 1)) * FF + lane];
      const float ss2 = warpsum(v * v);
      float sc = rsqrtf(ss2);
      if (s) sc *= (1.0f / DEG);
      Ws[k * LP + s * FF + lane] = v * sc;
    }
  }

  asm volatile("cp.async.wait_group 0;" ::: "memory");
  __syncthreads();

  // ---- Phase C: L2-normalize rows in place (packed f32x2 math).
  {
    constexpr int G = RTOT / 4;
    const int c  = lane & 7;
    const int rg = lane >> 3;
    #pragma unroll 1
    for (int g0 = w; g0 < G; g0 += NWARP * 4){
      ulonglong2 v[4]; int off[4]; bool val[4];
      #pragma unroll
      for (int u = 0; u < 4; u++){
        const int g = g0 + u * NWARP;
        const int r = g * 4 + rg;
        const int nn = r / RPG, ss = r - nn * RPG;
        val[u] = (g < G) && (nn < count);
        off[u] = nn * LP + ss * FF + c * 4;
        if (val[u]) v[u] = *(const ulonglong2*)&Xs[off[u]];
        else { v[u].x = 0ULL; v[u].y = 0ULL; }
      }
      #pragma unroll
      for (int u = 0; u < 4; u++){
        const unsigned long long sq = ffma2(v[u].y, v[u].y, fmul2(v[u].x, v[u].x));
        const float2 sp = unpack2(sq);
        const float ssq = grp8sum(sp.x + sp.y);
        const float sc = (ssq > 0.0f) ? rsqrtf(ssq) : 0.0f;
        if (val[u]){
          const unsigned long long sc2 = pack2(sc, sc);
          ulonglong2 o;
          o.x = fmul2(v[u].x, sc2);
          o.y = fmul2(v[u].y, sc2);
          *(ulonglong2*)&Xs[off[u]] = o;
        }
      }
    }
  }
  __syncthreads();

  // ---- Phase 2: register-tiled GEMM (f32x2), feature-split across lanes;
  // fs==0 lanes write the FULL 256B output row (scores + zeros).
  {
    constexpr int KG = KK / TK;        // kernel groups
    const int kg  = lane >> (1 + (FS == 2 ? 1 : 2));
    const int fs  = (lane >> 1) & (FS - 1);
    const int ng  = (w << 1) | (lane & 1);

    unsigned long long acc[TN][TK];
    #pragma unroll
    for (int i = 0; i < TN; i++)
      #pragma unroll
      for (int j = 0; j < TK; j++) acc[i][j] = 0ULL;

    const float* xb = Xs + (ng * TN) * LP + fs * 4;
    const float* wb = Ws + (kg * TK) * LP + fs * 4;
    constexpr int CHUNKS = L / (4 * FS);

    #pragma unroll
    for (int cidx = 0; cidx < CHUNKS; cidx++){
      const int off = cidx * 4 * FS;
      ulonglong2 xv[TN], wv[TK];
      #pragma unroll
      for (int i = 0; i < TN; i++)
        xv[i] = *(const ulonglong2*)(xb + i * LP + off);
      #pragma unroll
      for (int j = 0; j < TK; j++)
        wv[j] = *(const ulonglong2*)(wb + j * LP + off);
      #pragma unroll
      for (int i = 0; i < TN; i++){
        #pragma unroll
        for (int j = 0; j < TK; j++){
          acc[i][j] = ffma2(xv[i].x, wv[j].x, acc[i][j]);
          acc[i][j] = ffma2(xv[i].y, wv[j].y, acc[i][j]);
        }
      }
    }

    // cross-fs reduction (fs lives in lane bits starting at bit 1)
    #pragma unroll
    for (int mask = 2; mask < 2 * FS; mask <<= 1){
      #pragma unroll
      for (int i = 0; i < TN; i++)
        #pragma unroll
        for (int j = 0; j < TK; j++){
          unsigned long long o = __shfl_xor_sync(0xffffffffu, acc[i][j], mask);
          acc[i][j] = fadd2(acc[i][j], o);
        }
    }

    if (fs == 0){
      #pragma unroll
      for (int i = 0; i < TN; i++){
        const int n = ng * TN + i;
        if (n < count){
          const unsigned node = (unsigned)Rs[n * RPG];
          float s[TK];
          #pragma unroll
          for (int j = 0; j < TK; j++){
            const float2 a = unpack2(acc[i][j]);
            s[j] = a.x + a.y;
          }
          float* row = &out[(size_t)(node * 64u)];
          // writer kg covers vector slots {kg + KG*m : m=0..3}; the slot with
          // m == DEG-1 holds this kg's scores, the rest are zeros.
          #pragma unroll
          for (int m = 0; m < 4; m++){
            float* dst = row + (kg + KG * m) * TK;
            if (TK == 4){
              float4 v4;
              if (m == DEG - 1){ v4.x = s[0]; v4.y = s[1]; v4.z = s[2]; v4.w = s[3]; }
              else { v4.x = 0.f; v4.y = 0.f; v4.z = 0.f; v4.w = 0.f; }
              *(float4*)dst = v4;
            } else {
              float2 v2;
              if (m == DEG - 1){ v2.x = s[0]; v2.y = s[1]; }
              else { v2.x = 0.f; v2.y = 0.f; }
              *(float2*)dst = v2;
            }
          }
        }
      }
    }
  }
}

static inline int smem_bytes(int deg){
  const int LP = (1 + deg) * FF + 4;
  const int RTOT = NT * (1 + deg);
  return ((NT + KK) * LP) * (int)sizeof(float) + RTOT * (int)sizeof(int);
}

extern "C" void kernel_launch(void* const* d_in, const int* in_sizes, int n_in,
                              void* d_out, int out_size)
{
  const float* x = (const float*)d_in[0];
  const void *sel[4], *nei[4];
  const float *Wf[4], *Wn[4];
  int Nd[4];

  if (in_sizes[1] == 512){
    // reference-signature order: x, (Wf,Wn)x4, sel1..4, nei1..4
    for (int d = 0; d < 4; d++){
      Wf[d]  = (const float*)d_in[1 + 2 * d];
      Wn[d]  = (const float*)d_in[2 + 2 * d];
      sel[d] = d_in[9 + d];
      nei[d] = d_in[13 + d];
      Nd[d]  = in_sizes[9 + d];
    }
  } else {
    // setup_inputs dict order: x, then (sel, nei, Wf, Wn) per degree
    int b = 1;
    for (int d = 0; d < 4; d++){
      sel[d] = d_in[b + 0];
      nei[d] = d_in[b + 1];
      Wf[d]  = (const float*)d_in[b + 2];
      Wn[d]  = (const float*)d_in[b + 3];
      Nd[d]  = in_sizes[b + 0];
      b += 4;
    }
  }

  float* out = (float*)d_out;

  cudaFuncSetAttribute((const void*)score_kernel<1,4,2,2,4>, cudaFuncAttributeMaxDynamicSharedMemorySize, smem_bytes(1));
  cudaFuncSetAttribute((const void*)score_kernel<2,4,2,2,4>, cudaFuncAttributeMaxDynamicSharedMemorySize, smem_bytes(2));
  cudaFuncSetAttribute((const void*)score_kernel<3,4,4,4,3>, cudaFuncAttributeMaxDynamicSharedMemorySize, smem_bytes(3));
  cudaFuncSetAttribute((const void*)score_kernel<4,4,4,4,3>, cudaFuncAttributeMaxDynamicSharedMemorySize, smem_bytes(4));

  score_kernel<4,4,4,4,3><<<(Nd[3] + NT - 1) / NT, NTHREADS, smem_bytes(4)>>>(
      x, sel[3], nei[3], Wf[3], Wn[3], out, Nd[3]);
  score_kernel<3,4,4,4,3><<<(Nd[2] + NT - 1) / NT, NTHREADS, smem_bytes(3)>>>(
      x, sel[2], nei[2], Wf[2], Wn[2], out, Nd[2]);
  score_kernel<2,4,2,2,4><<<(Nd[1] + NT - 1) / NT, NTHREADS, smem_bytes(2)>>>(
      x, sel[1], nei[1], Wf[1], Wn[1], out, Nd[1]);
  score_kernel<1,4,2,2,4><<<(Nd[0] + NT - 1) / NT, NTHREADS, smem_bytes(1)>>>(
      x, sel[0], nei[0], Wf[0], Wn[0], out, Nd[0]);
}

// round 13
// speedup vs baseline: 1.0980x; 1.0871x over previous
#include <cuda_runtime.h>
#include <cstdint>
#include <cstring>

#define KK 16
#define FF 32
#define NT 64
#define NTHREADS 256
#define NWARP (NTHREADS/32)

__device__ __forceinline__ float warpsum(float v){
  #pragma unroll
  for (int o = 16; o > 0; o >>= 1) v += __shfl_xor_sync(0xffffffffu, v, o);
  return v;
}

__device__ __forceinline__ float grp8sum(float v){
  v += __shfl_xor_sync(0xffffffffu, v, 1);
  v += __shfl_xor_sync(0xffffffffu, v, 2);
  v += __shfl_xor_sync(0xffffffffu, v, 4);
  return v;
}

// packed f32x2 ops (sm_100+; not reachable from C++)
__device__ __forceinline__ unsigned long long ffma2(unsigned long long a,
                                                    unsigned long long b,
                                                    unsigned long long c){
  unsigned long long d;
  asm("fma.rn.f32x2 %0, %1, %2, %3;" : "=l"(d) : "l"(a), "l"(b), "l"(c));
  return d;
}
__device__ __forceinline__ unsigned long long fmul2(unsigned long long a,
                                                    unsigned long long b){
  unsigned long long d;
  asm("mul.rn.f32x2 %0, %1, %2;" : "=l"(d) : "l"(a), "l"(b));
  return d;
}
__device__ __forceinline__ unsigned long long fadd2(unsigned long long a,
                                                    unsigned long long b){
  unsigned long long d;
  asm("add.rn.f32x2 %0, %1, %2;" : "=l"(d) : "l"(a), "l"(b));
  return d;
}
__device__ __forceinline__ float2 unpack2(unsigned long long a){
  float2 f;
  asm("mov.b64 {%0, %1}, %2;" : "=f"(f.x), "=f"(f.y) : "l"(a));
  return f;
}
__device__ __forceinline__ unsigned long long pack2(float lo, float hi){
  unsigned long long d;
  asm("mov.b64 %0, {%1, %2};" : "=l"(d) : "f"(lo), "f"(hi));
  return d;
}

__device__ __forceinline__ uint32_t smem_u32(const void* p){
  uint32_t a;
  asm("{ .reg .u64 t; cvta.to.shared.u64 t, %1; cvt.u32.u64 %0, t; }"
      : "=r"(a) : "l"(p));
  return a;
}

__device__ __forceinline__ void cp_async16(uint32_t dst, const void* src){
  asm volatile("cp.async.cg.shared.global [%0], [%1], 16;"
               :: "r"(dst), "l"(src));
}

// int64 vs int32 index array detection (node ids < 2^31)
__device__ __forceinline__ int is64_flag(const void* p){
  const unsigned int* u = (const unsigned int*)p;
  return ((u[1] | u[3] | u[5] | u[7]) == 0u) ? 1 : 0;
}
__device__ __forceinline__ int ldidx32(const void* p, int i, int is64){
  return is64 ? ((const int*)p)[2 * i] : ((const int*)p)[i];
}

// DEG: degree; TN x TK: per-thread node x kernel tile; FS: feature-split ways.
template<int DEG, int TN, int TK, int FS, int MINB>
__global__ void __launch_bounds__(NTHREADS, MINB) score_kernel(
    const float* __restrict__ x,
    const void* __restrict__ sel,
    const void* __restrict__ nei,
    const float* __restrict__ Wf,
    const float* __restrict__ Wn,
    float* __restrict__ out,
    int Nd)
{
  constexpr int RPG  = 1 + DEG;
  constexpr int L    = RPG * FF;
  constexpr int LP   = L + 4;           // 16B-aligned stride, ==4 (mod 8)
  constexpr int RTOT = NT * RPG;

  extern __shared__ float smem[];
  float* Xs = smem;                               // NT * LP
  float* Ws = smem + NT * LP;                     // KK * LP
  int*   Rs = (int*)(smem + NT * LP + KK * LP);   // RTOT row ids

  const int tid  = threadIdx.x;
  const int w    = tid >> 5;
  const int lane = tid & 31;
  const int tile = blockIdx.x * NT;
  const int count = min(NT, Nd - tile);
  const int s64 = is64_flag(sel);
  const int n64 = is64_flag(nei);

  // ---- Phase A: stage row ids into SMEM (coalesced).
  #pragma unroll
  for (int r = tid; r < RTOT; r += NTHREADS){
    const int nn = r / RPG, ss = r - nn * RPG;
    int id = 0;
    if (nn < count)
      id = (ss == 0) ? ldidx32(sel, tile + nn, s64)
                     : ldidx32(nei, (tile + nn) * DEG + ss - 1, n64);
    Rs[r] = id;
  }
  __syncthreads();

  // ---- Phase B: whole gather via cp.async (GMEM -> SMEM, no RF).
  {
    const int c  = tid & 7;
    const int rb = tid >> 3;
    constexpr int ITER = RTOT / 32;
    constexpr int DNN = 32 / RPG, DSS = 32 % RPG;
    const uint32_t xs0 = smem_u32(Xs) + (uint32_t)(c * 16);
    int nn = rb / RPG, ss = rb - nn * RPG;
    #pragma unroll
    for (int i = 0; i < ITER; i++){
      if (nn < count){
        const unsigned id = (unsigned)Rs[rb + 32 * i];
        const float* src = x + (size_t)(id * (unsigned)FF) + c * 4;
        const uint32_t dst = xs0 + (uint32_t)((nn * LP + ss * FF) * 4);
        cp_async16(dst, src);
      }
      ss += DSS;
      const int wrap = (ss >= RPG);
      if (wrap) ss -= RPG;
      nn += DNN + wrap;
    }
    asm volatile("cp.async.commit_group;");
  }

  // ---- Phase 0 (overlaps gather): normalize weights into SMEM.
  {
    constexpr int RW = KK * RPG;
    for (int r = w; r < RW; r += NWARP){
      const int k = r / RPG, s = r % RPG;
      float v = (s == 0) ? Wf[k * FF + lane]
                         : Wn[(k * DEG + (s - 1)) * FF + lane];
      const float ss2 = warpsum(v * v);
      float sc = rsqrtf(ss2);
      if (s) sc *= (1.0f / DEG);
      Ws[k * LP + s * FF + lane] = v * sc;
    }
  }

  // ---- Phase D (overlaps gather): zero-fill the 48 non-score output columns.
  // Needs only Rs (ready) — coalesced 192B per node row, hidden under cp.async.
  {
    const int col = lane * 4 + ((lane * 4 >= 16 * (DEG - 1)) ? 16 : 0);
    const bool wr = (lane < 12);
    const float4 z = make_float4(0.f, 0.f, 0.f, 0.f);
    for (int n = w; n < count; n += NWARP){
      const unsigned node = (unsigned)Rs[n * RPG];
      if (wr) *(float4*)&out[(size_t)(node * 64u) + col] = z;
    }
  }

  asm volatile("cp.async.wait_group 0;" ::: "memory");
  __syncthreads();

  // ---- Phase C: L2-normalize rows in place (packed f32x2 math).
  {
    constexpr int G = RTOT / 4;
    const int c  = lane & 7;
    const int rg = lane >> 3;
    #pragma unroll 1
    for (int g0 = w; g0 < G; g0 += NWARP * 4){
      ulonglong2 v[4]; int off[4]; bool val[4];
      #pragma unroll
      for (int u = 0; u < 4; u++){
        const int g = g0 + u * NWARP;
        const int r = g * 4 + rg;
        const int nn = r / RPG, ss = r - nn * RPG;
        val[u] = (g < G) && (nn < count);
        off[u] = nn * LP + ss * FF + c * 4;
        if (val[u]) v[u] = *(const ulonglong2*)&Xs[off[u]];
        else { v[u].x = 0ULL; v[u].y = 0ULL; }
      }
      #pragma unroll
      for (int u = 0; u < 4; u++){
        const unsigned long long sq = ffma2(v[u].y, v[u].y, fmul2(v[u].x, v[u].x));
        const float2 sp = unpack2(sq);
        const float ssq = grp8sum(sp.x + sp.y);
        const float sc = (ssq > 0.0f) ? rsqrtf(ssq) : 0.0f;
        if (val[u]){
          const unsigned long long sc2 = pack2(sc, sc);
          ulonglong2 o;
          o.x = fmul2(v[u].x, sc2);
          o.y = fmul2(v[u].y, sc2);
          *(ulonglong2*)&Xs[off[u]] = o;
        }
      }
    }
  }
  __syncthreads();

  // ---- Phase 2: register-tiled GEMM (f32x2), feature-split across lanes;
  // fs==0 lanes write the TK-wide score block per node.
  {
    const int kg  = lane >> (1 + (FS == 2 ? 1 : 2));
    const int fs  = (lane >> 1) & (FS - 1);
    const int ng  = (w << 1) | (lane & 1);

    unsigned long long acc[TN][TK];
    #pragma unroll
    for (int i = 0; i < TN; i++)
      #pragma unroll
      for (int j = 0; j < TK; j++) acc[i][j] = 0ULL;

    const float* xb = Xs + (ng * TN) * LP + fs * 4;
    const float* wb = Ws + (kg * TK) * LP + fs * 4;
    constexpr int CHUNKS = L / (4 * FS);

    #pragma unroll
    for (int cidx = 0; cidx < CHUNKS; cidx++){
      const int off = cidx * 4 * FS;
      ulonglong2 xv[TN], wv[TK];
      #pragma unroll
      for (int i = 0; i < TN; i++)
        xv[i] = *(const ulonglong2*)(xb + i * LP + off);
      #pragma unroll
      for (int j = 0; j < TK; j++)
        wv[j] = *(const ulonglong2*)(wb + j * LP + off);
      #pragma unroll
      for (int i = 0; i < TN; i++){
        #pragma unroll
        for (int j = 0; j < TK; j++){
          acc[i][j] = ffma2(xv[i].x, wv[j].x, acc[i][j]);
          acc[i][j] = ffma2(xv[i].y, wv[j].y, acc[i][j]);
        }
      }
    }

    // cross-fs reduction (fs lives in lane bits starting at bit 1)
    #pragma unroll
    for (int mask = 2; mask < 2 * FS; mask <<= 1){
      #pragma unroll
      for (int i = 0; i < TN; i++)
        #pragma unroll
        for (int j = 0; j < TK; j++){
          unsigned long long o = __shfl_xor_sync(0xffffffffu, acc[i][j], mask);
          acc[i][j] = fadd2(acc[i][j], o);
        }
    }

    if (fs == 0){
      #pragma unroll
      for (int i = 0; i < TN; i++){
        const int n = ng * TN + i;
        if (n < count){
          const unsigned node = (unsigned)Rs[n * RPG];
          float s[TK];
          #pragma unroll
          for (int j = 0; j < TK; j++){
            const float2 a = unpack2(acc[i][j]);
            s[j] = a.x + a.y;
          }
          float* dst = &out[(size_t)(node * 64u) + (DEG - 1) * 16 + kg * TK];
          if (TK == 4){
            float4 v4; v4.x = s[0]; v4.y = s[1]; v4.z = s[2]; v4.w = s[3];
            *(float4*)dst = v4;
          } else {
            float2 v2; v2.x = s[0]; v2.y = s[1];
            *(float2*)dst = v2;
          }
        }
      }
    }
  }
}

static inline int smem_bytes(int deg){
  const int LP = (1 + deg) * FF + 4;
  const int RTOT = NT * (1 + deg);
  return ((NT + KK) * LP) * (int)sizeof(float) + RTOT * (int)sizeof(int);
}

extern "C" void kernel_launch(void* const* d_in, const int* in_sizes, int n_in,
                              void* d_out, int out_size)
{
  const float* x = (const float*)d_in[0];
  const void *sel[4], *nei[4];
  const float *Wf[4], *Wn[4];
  int Nd[4];

  if (in_sizes[1] == 512){
    // reference-signature order: x, (Wf,Wn)x4, sel1..4, nei1..4
    for (int d = 0; d < 4; d++){
      Wf[d]  = (const float*)d_in[1 + 2 * d];
      Wn[d]  = (const float*)d_in[2 + 2 * d];
      sel[d] = d_in[9 + d];
      nei[d] = d_in[13 + d];
      Nd[d]  = in_sizes[9 + d];
    }
  } else {
    // setup_inputs dict order: x, then (sel, nei, Wf, Wn) per degree
    int b = 1;
    for (int d = 0; d < 4; d++){
      sel[d] = d_in[b + 0];
      nei[d] = d_in[b + 1];
      Wf[d]  = (const float*)d_in[b + 2];
      Wn[d]  = (const float*)d_in[b + 3];
      Nd[d]  = in_sizes[b + 0];
      b += 4;
    }
  }

  float* out = (float*)d_out;

  // Side streams + fork/join events, created once on the first (uncaptured)
  // correctness call. Host objects only — no device allocation.
  static cudaStream_t s_str[3];
  static cudaEvent_t  s_fork, s_join[3];
  static bool s_init = false;
  if (!s_init){
    for (int i = 0; i < 3; i++)
      cudaStreamCreateWithFlags(&s_str[i], cudaStreamNonBlocking);
    cudaEventCreateWithFlags(&s_fork, cudaEventDisableTiming);
    for (int i = 0; i < 3; i++)
      cudaEventCreateWithFlags(&s_join[i], cudaEventDisableTiming);
    s_init = true;
  }

  cudaFuncSetAttribute((const void*)score_kernel<1,4,2,2,4>, cudaFuncAttributeMaxDynamicSharedMemorySize, smem_bytes(1));
  cudaFuncSetAttribute((const void*)score_kernel<2,4,2,2,4>, cudaFuncAttributeMaxDynamicSharedMemorySize, smem_bytes(2));
  cudaFuncSetAttribute((const void*)score_kernel<3,4,4,4,3>, cudaFuncAttributeMaxDynamicSharedMemorySize, smem_bytes(3));
  cudaFuncSetAttribute((const void*)score_kernel<4,4,4,4,3>, cudaFuncAttributeMaxDynamicSharedMemorySize, smem_bytes(4));

  // fork: side streams depend on everything already in the main stream
  cudaEventRecord(s_fork, 0);
  for (int i = 0; i < 3; i++) cudaStreamWaitEvent(s_str[i], s_fork, 0);

  score_kernel<4,4,4,4,3><<<(Nd[3] + NT - 1) / NT, NTHREADS, smem_bytes(4), 0>>>(
      x, sel[3], nei[3], Wf[3], Wn[3], out, Nd[3]);
  score_kernel<3,4,4,4,3><<<(Nd[2] + NT - 1) / NT, NTHREADS, smem_bytes(3), s_str[0]>>>(
      x, sel[2], nei[2], Wf[2], Wn[2], out, Nd[2]);
  score_kernel<2,4,2,2,4><<<(Nd[1] + NT - 1) / NT, NTHREADS, smem_bytes(2), s_str[1]>>>(
      x, sel[1], nei[1], Wf[1], Wn[1], out, Nd[1]);
  score_kernel<1,4,2,2,4><<<(Nd[0] + NT - 1) / NT, NTHREADS, smem_bytes(1), s_str[2]>>>(
      x, sel[0], nei[0], Wf[0], Wn[0], out, Nd[0]);

  // join: main stream waits for all side streams
  for (int i = 0; i < 3; i++){
    cudaEventRecord(s_join[i], s_str[i]);
    cudaStreamWaitEvent(0, s_join[i], 0);
  }
}